// round 11
// baseline (speedup 1.0000x reference)
#include <cuda_runtime.h>
#include <cuda_bf16.h>
#include <cstdint>

// ---------------- problem dims ----------------
#define TT 1024
#define BB 8
#define DD 1024
#define HH 16
#define ROWS 8192
#define SEGC 8388608u
#define KC 3072                 // concatenated split-bf16 K (hi|hi|lo vs hi|lo|hi)

typedef unsigned long long ull;

// ---------------- device scratch ----------------
__device__ float g_proj[5ull * SEGC];     // q,k,v,apre,bpre (fp32)
__device__ float g_alpha[ROWS * HH];
__device__ float g_beta[ROWS * HH];
__device__ __align__(16) __nv_bfloat16 g_xcat[(size_t)ROWS * KC];   // 48 MB
__device__ __align__(16) __nv_bfloat16 g_wcat[(size_t)5120 * KC];   // 30 MB

// ---------------- helpers ----------------
__device__ __forceinline__ uint32_t smem_u32(const void* p) {
    uint32_t a;
    asm("{ .reg .u64 t; cvta.to.shared.u64 t, %1; cvt.u32.u64 %0, t; }" : "=r"(a) : "l"(p));
    return a;
}
__device__ __forceinline__ void cpa16(uint32_t dst, const void* src) {
    asm volatile("cp.async.cg.shared.global [%0], [%1], 16;" :: "r"(dst), "l"(src));
}
#define CP_COMMIT() asm volatile("cp.async.commit_group;")
#define CP_WAIT2()  asm volatile("cp.async.wait_group 2;")

__device__ __forceinline__ void ldm4(uint32_t* r, uint32_t a) {
    asm volatile("ldmatrix.sync.aligned.m8n8.x4.shared.b16 {%0,%1,%2,%3}, [%4];"
        : "=r"(r[0]), "=r"(r[1]), "=r"(r[2]), "=r"(r[3]) : "r"(a));
}
__device__ __forceinline__ void mma16816(float* d, const uint32_t* a, uint32_t b0, uint32_t b1) {
    asm volatile(
        "mma.sync.aligned.m16n8k16.row.col.f32.bf16.bf16.f32 "
        "{%0,%1,%2,%3},{%4,%5,%6,%7},{%8,%9},{%0,%1,%2,%3};"
        : "+f"(d[0]), "+f"(d[1]), "+f"(d[2]), "+f"(d[3])
        : "r"(a[0]), "r"(a[1]), "r"(a[2]), "r"(a[3]), "r"(b0), "r"(b1));
}

// packed f32x2 (sm_100+ FFMA2)
#define FMA2(d, a, b, c) asm("fma.rn.f32x2 %0, %1, %2, %3;" : "=l"(d) : "l"(a), "l"(b), "l"(c))
#define MUL2(d, a, b)    asm("mul.rn.f32x2 %0, %1, %2;"     : "=l"(d) : "l"(a), "l"(b))
#define PK2(d, x, y)     asm("mov.b64 %0, {%1, %2};"        : "=l"(d) : "f"(x), "f"(y))
#define UNPK2(x, y, d)   asm("mov.b64 {%0, %1}, %2;"        : "=f"(x), "=f"(y) : "l"(d))

// split one float into bf16 hi + bf16 lo
__device__ __forceinline__ void split2(float f0, float f1, uint32_t& hw, uint32_t& lw) {
    __nv_bfloat16 h0 = __float2bfloat16(f0);
    __nv_bfloat16 h1 = __float2bfloat16(f1);
    __nv_bfloat16 l0 = __float2bfloat16(f0 - __bfloat162float(h0));
    __nv_bfloat16 l1 = __float2bfloat16(f1 - __bfloat162float(h1));
    hw = (uint32_t)__bfloat16_as_ushort(h0) | ((uint32_t)__bfloat16_as_ushort(h1) << 16);
    lw = (uint32_t)__bfloat16_as_ushort(l0) | ((uint32_t)__bfloat16_as_ushort(l1) << 16);
}

// =====================================================================
// pack_all: fused pack_x + pack_w (unchanged from R8/R9).
// =====================================================================
__global__ __launch_bounds__(256)
void pack_all(const float* __restrict__ x,
              const float* __restrict__ W0, const float* __restrict__ W1,
              const float* __restrict__ W2, const float* __restrict__ W3,
              const float* __restrict__ W4)
{
    unsigned idx = blockIdx.x * 256 + threadIdx.x;
    if (idx < 1048576u) {
        unsigned e = idx * 8;
        unsigned row = e >> 10, col = e & 1023;
        float4 f0 = *(const float4*)(x + e);
        float4 f1 = *(const float4*)(x + e + 4);
        uint4 hi, lo;
        split2(f0.x, f0.y, hi.x, lo.x);
        split2(f0.z, f0.w, hi.y, lo.y);
        split2(f1.x, f1.y, hi.z, lo.z);
        split2(f1.z, f1.w, hi.w, lo.w);
        __nv_bfloat16* base = g_xcat + (size_t)row * KC;
        *(uint4*)(base + col)        = hi;
        *(uint4*)(base + col + 1024) = hi;
        *(uint4*)(base + col + 2048) = lo;
    } else {
        unsigned j = idx - 1048576u;
        unsigned e = j * 8;
        unsigned seg = e >> 20;
        unsigned n = (e >> 10) & 1023, k = e & 1023;
        const float* W = (seg == 0) ? W0 : (seg == 1) ? W1 : (seg == 2) ? W2
                         : (seg == 3) ? W3 : W4;
        const float* src = W + (size_t)n * 1024 + k;
        float4 f0 = *(const float4*)(src);
        float4 f1 = *(const float4*)(src + 4);
        uint4 hi, lo;
        split2(f0.x, f0.y, hi.x, lo.x);
        split2(f0.z, f0.w, hi.y, lo.y);
        split2(f1.x, f1.y, hi.z, lo.z);
        split2(f1.z, f1.w, hi.w, lo.w);
        __nv_bfloat16* base = g_wcat + (size_t)(seg * 1024 + n) * KC;
        *(uint4*)(base + k)        = hi;
        *(uint4*)(base + k + 1024) = lo;
        *(uint4*)(base + k + 2048) = hi;
    }
}

// =====================================================================
// gemm_mma: unchanged R8 config (best measured: 752.9us, tensor 56.6%).
// =====================================================================
#define STG 20480

__global__ __launch_bounds__(256, 2)
void gemm_mma()
{
    extern __shared__ __align__(16) unsigned char sm[];
    const uint32_t smb = smem_u32(sm);

    const int bid = blockIdx.x;
    const int mt = bid / 40, nt = bid % 40;
    const int tid = threadIdx.x;
    const int lane = tid & 31, wid = tid >> 5;
    const int wm = wid & 1, wn = wid >> 1;

    const int lrow = tid >> 2, lch = tid & 3;
    const __nv_bfloat16* Ag = g_xcat + (size_t)(mt * 128 + lrow) * KC + lch * 8;
    const __nv_bfloat16* Bg = g_wcat + (size_t)(nt * 128 + lrow) * KC + lch * 8;
    const uint32_t sA = smb + lrow * 80 + lch * 16;
    const uint32_t sB = smb + 10240 + lrow * 80 + lch * 16;

    auto load = [&](int it, int stage) {
        const uint32_t off = stage * STG;
        const __nv_bfloat16* ag = Ag + it * 32;
        const __nv_bfloat16* bg = Bg + it * 32;
        cpa16(sA + off,           ag);
        cpa16(sA + off + 64 * 80, ag + (size_t)64 * KC);
        cpa16(sB + off,           bg);
        cpa16(sB + off + 64 * 80, bg + (size_t)64 * KC);
    };

    uint32_t aAddr[4], bAddr[2];
#pragma unroll
    for (int f = 0; f < 4; f++)
        aAddr[f] = smb + (wm * 64 + f * 16 + (lane & 15)) * 80 + (lane >> 4) * 16;
#pragma unroll
    for (int x = 0; x < 2; x++)
        bAddr[x] = smb + 10240 + (wn * 32 + x * 16 + (lane & 15)) * 80 + (lane >> 4) * 16;

    float acc[4][4][4];
#pragma unroll
    for (int f = 0; f < 4; f++)
#pragma unroll
        for (int g = 0; g < 4; g++)
#pragma unroll
            for (int i = 0; i < 4; i++) acc[f][g][i] = 0.f;

    load(0, 0); CP_COMMIT();
    load(1, 1); CP_COMMIT();
    load(2, 2); CP_COMMIT();

    const int NIT = KC / 32;    // 96
    for (int it = 0; it < NIT; it++) {
        CP_WAIT2();
        __syncthreads();
        if (it + 3 < NIT) load(it + 3, (it + 3) & 3);
        CP_COMMIT();

        const uint32_t st = (it & 3) * STG;
#pragma unroll
        for (int ks = 0; ks < 2; ks++) {
            uint32_t af[4][4], bf[2][4];
#pragma unroll
            for (int f = 0; f < 4; f++) ldm4(af[f], aAddr[f] + st + ks * 32);
#pragma unroll
            for (int x = 0; x < 2; x++) ldm4(bf[x], bAddr[x] + st + ks * 32);
#pragma unroll
            for (int f = 0; f < 4; f++) {
#pragma unroll
                for (int g = 0; g < 4; g++) {
                    const uint32_t b0 = bf[g >> 1][g & 1];
                    const uint32_t b1 = bf[g >> 1][(g & 1) + 2];
                    mma16816(acc[f][g], af[f], b0, b1);
                }
            }
        }
    }

    const int seg = nt >> 3;
    float* op = g_proj + (size_t)seg * SEGC;
    const int rbase = mt * 128 + wm * 64 + (lane >> 2);
    const int cbase = (nt & 7) * 128 + wn * 32 + (lane & 3) * 2;
#pragma unroll
    for (int f = 0; f < 4; f++) {
#pragma unroll
        for (int g = 0; g < 4; g++) {
            const int r = rbase + f * 16;
            const int c = cbase + g * 8;
            float2 v0 = make_float2(acc[f][g][0], acc[f][g][1]);
            float2 v1 = make_float2(acc[f][g][2], acc[f][g][3]);
            *(float2*)(op + (size_t)r * 1024 + c)       = v0;
            *(float2*)(op + (size_t)(r + 8) * 1024 + c) = v1;
        }
    }
}

// =====================================================================
// postproc: unchanged.
// =====================================================================
__device__ __forceinline__ float sigf(float x) { return 1.0f / (1.0f + expf(-x)); }

__global__ __launch_bounds__(256)
void postproc(const float* __restrict__ b_alpha, const float* __restrict__ b_beta)
{
    const int wid = threadIdx.x >> 5;
    const int lane = threadIdx.x & 31;
    const int gb = blockIdx.x * 8 + wid;   // tb*16 + h
    const int h = gb & 15;
    const size_t row = (size_t)(gb >> 4) * DD + h * 64 + lane * 2;

    float2 q  = *(float2*)(g_proj + row);
    float2 k  = *(float2*)(g_proj + (size_t)SEGC + row);
    float2 ap = *(float2*)(g_proj + 3ull * SEGC + row);
    float2 bp = *(float2*)(g_proj + 4ull * SEGC + row);
    float2 ba = *(const float2*)(b_alpha + h * 64 + lane * 2);
    float2 bbv = *(const float2*)(b_beta + h * 64 + lane * 2);

    float sq = fmaf(q.x, q.x, q.y * q.y);
    float sk = fmaf(k.x, k.x, k.y * k.y);
    float sa = sigf(ap.x + ba.x) + sigf(ap.y + ba.y);
    float sb = sigf(bp.x + bbv.x) + sigf(bp.y + bbv.y);
#pragma unroll
    for (int m = 16; m; m >>= 1) {
        sq += __shfl_xor_sync(0xffffffffu, sq, m);
        sk += __shfl_xor_sync(0xffffffffu, sk, m);
        sa += __shfl_xor_sync(0xffffffffu, sa, m);
        sb += __shfl_xor_sync(0xffffffffu, sb, m);
    }
    const float qi = 1.0f / fmaxf(sqrtf(sq), 1e-12f);
    const float ki = 1.0f / fmaxf(sqrtf(sk), 1e-12f);
    q.x *= qi; q.y *= qi;
    k.x *= ki; k.y *= ki;
    *(float2*)(g_proj + row) = q;
    *(float2*)(g_proj + (size_t)SEGC + row) = k;
    if (lane == 0) {
        g_alpha[gb] = sa * (1.0f / 64.0f);
        g_beta[gb]  = sb * (1.0f / 64.0f);
    }
}

// =====================================================================
// scan v5: chunked delta rule (UT transform), chunk C=64, 16 chunks.
// One CTA per (b,h), 512 threads. Everything in smem; FFMA2 math.
//   g_t = prod_{s<=t} a_s  (inclusive, within chunk)
//   u_t = b_t v_t - b_t g_t (S0 k_t)
//   W[t,s] = b_t (g_t/g_s)(k_s.k_t), s<t ; coef = (I+W)^-1 u (fwd subst,
//            independent per d -> warp-partitioned, __syncwarp only)
//   out_t = g_t (S0 q_t) + sum_{s<=t} (g_t/g_s)(k_s.q_t) coef_s
//   S'    = g_63 S0 + sum_s (g_63/g_s) coef_s k_s^T
// smem: 8 arrays [64][68] + gam/rg/alp/bet = 140,288 B.
// =====================================================================
#define PD 68
#define ARR (64 * PD)

__global__ __launch_bounds__(512, 1)
void scan(const float* __restrict__ S0, float* __restrict__ out)
{
    extern __shared__ float sp[];
    float* Ss = sp;               // S[d][e]
    float* Ksm = sp + ARR;        // K[t][e]
    float* Qsm = sp + 2 * ARR;    // Q[t][e]
    float* Vsm = sp + 3 * ARR;    // V[t][d]
    float* Wsm = sp + 4 * ARR;    // W[t][s]
    float* Asm = sp + 5 * ARR;    // A[t][s]
    float* Csm = sp + 6 * ARR;    // coef[t][d]
    float* Gsm = sp + 7 * ARR;    // sq0[t][d]
    float* gam = sp + 8 * ARR;
    float* rg  = gam + 64;
    float* alp = gam + 128;
    float* bet = gam + 192;

    const int bh = blockIdx.x;
    const int b = bh >> 4, h = bh & 15;
    const size_t base = (size_t)b * 1024 + h * 64;
    const int tid = threadIdx.x, lane = tid & 31, w = tid >> 5;

    // load initial state
    {
        int r = tid >> 3, c = (tid & 7) * 8;
        const float4* src = (const float4*)(S0 + ((size_t)bh * 64 + r) * 64 + c);
        *(float4*)&Ss[r * PD + c]     = src[0];
        *(float4*)&Ss[r * PD + c + 4] = src[1];
    }
    __syncthreads();

    const float* gq = g_proj + base;
    const float* gk = g_proj + (size_t)SEGC + base;
    const float* gv = g_proj + 2ull * SEGC + base;

    for (int c0 = 0; c0 < 16; c0++) {
        const int t0 = c0 * 64;
        // ---- (1) load chunk K,Q,V, alpha, beta ----
        {
            int r = tid >> 3, cc = (tid & 7) * 8;
            size_t g = (size_t)(t0 + r) * 8192 + cc;
            *(float4*)&Ksm[r * PD + cc]     = *(const float4*)(gk + g);
            *(float4*)&Ksm[r * PD + cc + 4] = *(const float4*)(gk + g + 4);
            *(float4*)&Qsm[r * PD + cc]     = *(const float4*)(gq + g);
            *(float4*)&Qsm[r * PD + cc + 4] = *(const float4*)(gq + g + 4);
            *(float4*)&Vsm[r * PD + cc]     = *(const float4*)(gv + g);
            *(float4*)&Vsm[r * PD + cc + 4] = *(const float4*)(gv + g + 4);
            if (tid < 64) {
                alp[tid] = g_alpha[(t0 + tid) * 128 + bh];
                bet[tid] = g_beta[(t0 + tid) * 128 + bh];
            }
        }
        __syncthreads();
        // ---- (2) inclusive product scan of alpha -> gam, rg ----
        if (w == 0) {
            float x = alp[lane];
#pragma unroll
            for (int off = 1; off < 32; off <<= 1) {
                float y = __shfl_up_sync(0xffffffffu, x, off);
                if (lane >= off) x *= y;
            }
            float tot = __shfl_sync(0xffffffffu, x, 31);
            float z = alp[32 + lane];
#pragma unroll
            for (int off = 1; off < 32; off <<= 1) {
                float y = __shfl_up_sync(0xffffffffu, z, off);
                if (lane >= off) z *= y;
            }
            z *= tot;
            gam[lane] = x;       gam[32 + lane] = z;
            rg[lane] = 1.0f / x; rg[32 + lane] = 1.0f / z;
        }
        __syncthreads();
        // ---- (3) u -> Csm ; sq0 -> Gsm ----
        {
            const int dd = tid & 63, tg = tid >> 6;   // warp-uniform t
            ull srow[32];
            const ulonglong2* sr2 = (const ulonglong2*)&Ss[dd * PD];
#pragma unroll
            for (int j = 0; j < 16; j++) { ulonglong2 v = sr2[j]; srow[2*j] = v.x; srow[2*j+1] = v.y; }
#pragma unroll
            for (int i = 0; i < 8; i++) {
                const int t = tg * 8 + i;
                ull ak = 0, aq = 0;
                const ulonglong2* kr = (const ulonglong2*)&Ksm[t * PD];
                const ulonglong2* qr = (const ulonglong2*)&Qsm[t * PD];
#pragma unroll
                for (int j = 0; j < 16; j++) {
                    ulonglong2 kv = kr[j], qv = qr[j];
                    FMA2(ak, srow[2*j],   kv.x, ak);
                    FMA2(aq, srow[2*j],   qv.x, aq);
                    FMA2(ak, srow[2*j+1], kv.y, ak);
                    FMA2(aq, srow[2*j+1], qv.y, aq);
                }
                float k0, k1, q0, q1;
                UNPK2(k0, k1, ak); UNPK2(q0, q1, aq);
                const float sk = k0 + k1, sq = q0 + q1;
                const float bt = bet[t], gt = gam[t];
                Csm[t * PD + dd] = bt * Vsm[t * PD + dd] - bt * gt * sk;
                Gsm[t * PD + dd] = sq;
            }
        }
        __syncthreads();
        // ---- (4) Grams: W (K.K) and A (K.Q), scaled + masked ----
        {
            const int ss = tid & 63, tg = tid >> 6;
            ull krow[32];
            const ulonglong2* kr2 = (const ulonglong2*)&Ksm[ss * PD];
#pragma unroll
            for (int j = 0; j < 16; j++) { ulonglong2 v = kr2[j]; krow[2*j] = v.x; krow[2*j+1] = v.y; }
            const float rgs = rg[ss];
#pragma unroll
            for (int i = 0; i < 8; i++) {
                const int t = tg * 8 + i;
                ull akk = 0, akq = 0;
                const ulonglong2* kr = (const ulonglong2*)&Ksm[t * PD];
                const ulonglong2* qr = (const ulonglong2*)&Qsm[t * PD];
#pragma unroll
                for (int j = 0; j < 16; j++) {
                    ulonglong2 kv = kr[j], qv = qr[j];
                    FMA2(akk, krow[2*j],   kv.x, akk);
                    FMA2(akq, krow[2*j],   qv.x, akq);
                    FMA2(akk, krow[2*j+1], kv.y, akk);
                    FMA2(akq, krow[2*j+1], qv.y, akq);
                }
                float a0, a1, b0, b1;
                UNPK2(a0, a1, akk); UNPK2(b0, b1, akq);
                const float kk = a0 + a1, kq = b0 + b1;
                const float gt = gam[t];
                Wsm[t * PD + ss] = (ss < t)  ? bet[t] * gt * rgs * kk : 0.0f;
                Asm[t * PD + ss] = (ss <= t) ? gt * rgs * kq          : 0.0f;
            }
        }
        __syncthreads();
        // ---- (5) forward substitution (warp w owns d in [4w, 4w+4)) ----
        {
            const int p = lane & 1, trow = lane >> 1;
            const int dbase = w * 4 + p * 2;
            for (int s = 0; s < 63; s++) {
                const ull cs = *(const ull*)&Csm[s * PD + dbase];
                for (int t = s + 1 + trow; t < 64; t += 16) {
                    const float wv = Wsm[t * PD + s];
                    ull wp; PK2(wp, -wv, -wv);
                    ull cc = *(const ull*)&Csm[t * PD + dbase];
                    FMA2(cc, wp, cs, cc);
                    *(ull*)&Csm[t * PD + dbase] = cc;
                }
                __syncwarp();
            }
        }
        __syncthreads();
        // fold g_63 into rg (state-update factors); consumed in (7)
        if (tid < 64) rg[tid] *= gam[63];
        // ---- (6) outputs: warp w -> t = w*4+i; dd = 2*lane ----
        {
            const int dd = lane * 2;
#pragma unroll
            for (int i = 0; i < 4; i++) {
                const int t = w * 4 + i;
                ull acc = 0;
#pragma unroll 8
                for (int s = 0; s < 64; s++) {
                    const float av = Asm[t * PD + s];
                    ull ap; PK2(ap, av, av);
                    const ull cf = *(const ull*)&Csm[s * PD + dd];
                    FMA2(acc, ap, cf, acc);
                }
                const float gt = gam[t];
                ull gp; PK2(gp, gt, gt);
                const ull g2 = *(const ull*)&Gsm[t * PD + dd];
                FMA2(acc, gp, g2, acc);
                *(ull*)&out[(size_t)(t0 + t) * 8192 + base + dd] = acc;
            }
        }
        __syncthreads();
        // ---- (7) state update: S = g63*S + sum_s rg'[s]*coef_s (x) k_s ----
        {
            const int r = tid >> 3, cc = (tid & 7) * 8;
            const float gC = gam[63];
            ull gp; PK2(gp, gC, gC);
            ull acc[4];
            const ulonglong2* so = (const ulonglong2*)&Ss[r * PD + cc];
            {
                ulonglong2 v0 = so[0], v1 = so[1];
                MUL2(acc[0], gp, v0.x); MUL2(acc[1], gp, v0.y);
                MUL2(acc[2], gp, v1.x); MUL2(acc[3], gp, v1.y);
            }
            for (int s = 0; s < 64; s++) {
                const float f = Csm[s * PD + r] * rg[s];
                ull fp; PK2(fp, f, f);
                const ulonglong2* kr = (const ulonglong2*)&Ksm[s * PD + cc];
                ulonglong2 k0 = kr[0], k1 = kr[1];
                FMA2(acc[0], fp, k0.x, acc[0]);
                FMA2(acc[1], fp, k0.y, acc[1]);
                FMA2(acc[2], fp, k1.x, acc[2]);
                FMA2(acc[3], fp, k1.y, acc[3]);
            }
            ull* dst = (ull*)&Ss[r * PD + cc];
            dst[0] = acc[0]; dst[1] = acc[1]; dst[2] = acc[2]; dst[3] = acc[3];
        }
        __syncthreads();
    }

    // final state -> d_out tail region (B,H,DH,DH)
    {
        int r = tid >> 3, cc = (tid & 7) * 8;
        float4 v0 = *(const float4*)&Ss[r * PD + cc];
        float4 v1 = *(const float4*)&Ss[r * PD + cc + 4];
        float4* dst = (float4*)(out + (size_t)(TT * BB * DD) + ((size_t)bh * 64 + r) * 64 + cc);
        dst[0] = v0; dst[1] = v1;
    }
}

// =====================================================================
extern "C" void kernel_launch(void* const* d_in, const int* in_sizes, int n_in,
                              void* d_out, int out_size)
{
    const float* x  = (const float*)d_in[0];
    const float* S0 = (const float*)d_in[1];
    const float* Wq = (const float*)d_in[2];
    const float* Wk = (const float*)d_in[3];
    const float* Wv = (const float*)d_in[4];
    const float* Wa = (const float*)d_in[5];
    const float* ba = (const float*)d_in[6];
    const float* Wb = (const float*)d_in[7];
    const float* bb = (const float*)d_in[8];
    float* out = (float*)d_out;

    cudaFuncSetAttribute(gemm_mma, cudaFuncAttributeMaxDynamicSharedMemorySize, 4 * STG);
    cudaFuncSetAttribute(scan, cudaFuncAttributeMaxDynamicSharedMemorySize, 140288);

    pack_all<<<6656, 256>>>(x, Wq, Wk, Wv, Wa, Wb);
    gemm_mma<<<2560, 256, 4 * STG>>>();
    postproc<<<16384, 256>>>(ba, bb);
    scan<<<BB * HH, 512, 140288>>>(S0, out);   // 4th launch -> ncu capture slot
}